// round 2
// baseline (speedup 1.0000x reference)
#include <cuda_runtime.h>
#include <cuda_bf16.h>
#include <cstdint>

// ---------------------------------------------------------------------------
// Problem constants
// ---------------------------------------------------------------------------
#define BATCH     256
#define D_MODEL   2048
#define D_STATE   128
#define D_CONV    4
#define D_SSM     4096
#define NHEADS    64
#define HEADDIM   64
#define CONV_DIM  (D_SSM + 2 * D_STATE)              // 4352
#define D_IN_PROJ (2 * D_SSM + 2 * D_STATE + NHEADS) // 8512

#define OUT_N   (BATCH * D_MODEL)
#define CONV_N  (BATCH * CONV_DIM * D_CONV)
#define SSM_OFF (OUT_N + CONV_N)

// ---------------------------------------------------------------------------
// Scratch
// ---------------------------------------------------------------------------
__device__ float g_zxbcdt[(size_t)BATCH * D_IN_PROJ];
__device__ float g_act[(size_t)BATCH * CONV_DIM];
__device__ float g_yz[(size_t)BATCH * D_SSM];

// ---------------------------------------------------------------------------
// tf32 helpers
// ---------------------------------------------------------------------------
__device__ __forceinline__ float tf32_hi(float x) {
    return __uint_as_float(__float_as_uint(x) & 0xffffe000u);
}

__device__ __forceinline__ void mma_tf32(float* d,
    uint32_t a0, uint32_t a1, uint32_t a2, uint32_t a3,
    uint32_t b0, uint32_t b1)
{
    asm volatile(
        "mma.sync.aligned.m16n8k8.row.col.f32.tf32.tf32.f32 "
        "{%0,%1,%2,%3}, {%4,%5,%6,%7}, {%8,%9}, {%0,%1,%2,%3};\n"
        : "+f"(d[0]), "+f"(d[1]), "+f"(d[2]), "+f"(d[3])
        : "r"(a0), "r"(a1), "r"(a2), "r"(a3), "r"(b0), "r"(b1));
}

// ---------------------------------------------------------------------------
// Tensor-core GEMM: C[M,N] = A[M,K] @ B[N,K]^T   (3xTF32, fp32-level accuracy)
// Block tile 128x64x32, 256 threads (8 warps, 4x2 warp grid, 32x32 warp tile).
//
// smem layouts are fragment-native (swizzled at store time):
//   As[hl][mt][ks][lane][0..3]  -> one LDS.128 per m16k8 A fragment
//   Bs[nt][ks][lane][0..3]      -> one LDS.128 gives {b0hi,b1hi,b0lo,b1lo}
// ---------------------------------------------------------------------------
#define TBM 128
#define TBN 64
#define TBK 32
#define NKS (TBK / 8)   // 4
#define MTI (TBM / 16)  // 8
#define NTI (TBN / 8)   // 8

template <bool ATOMIC>
__global__ __launch_bounds__(256, 2) void gemm_tc(
    const float* __restrict__ A, const float* __restrict__ B,
    float* __restrict__ C, int M, int N, int K, int klen)
{
    __shared__ __align__(16) float As[2][MTI][NKS][32][4]; // 32 KB
    __shared__ __align__(16) float Bs[NTI][NKS][32][4];    // 16 KB

    const int tid  = threadIdx.x;
    const int lane = tid & 31;
    const int warp = tid >> 5;
    const int n0 = blockIdx.x * TBN;
    const int m0 = blockIdx.y * TBM;
    const int k0 = blockIdx.z * klen;
    const int wm = warp >> 1;   // 0..3
    const int wn = warp & 1;    // 0..1

    // global load mapping
    const int ar  = tid >> 1;        // A row 0..127
    const int akb = (tid & 1) * 16;  // A k base 0/16
    const int br  = tid >> 2;        // B row 0..63
    const int bkb = (tid & 3) * 8;   // B k base 0..24

    const float* Ag = A + (size_t)(m0 + ar) * K + k0 + akb;
    const float* Bg = B + (size_t)(n0 + br) * K + k0 + bkb;

    // prefetch chunk 0 into registers
    float4 afr[4], bfr[2];
#pragma unroll
    for (int q = 0; q < 4; q++) afr[q] = *(const float4*)(Ag + q * 4);
#pragma unroll
    for (int q = 0; q < 2; q++) bfr[q] = *(const float4*)(Bg + q * 4);

    float acc[2][4][4];
#pragma unroll
    for (int i = 0; i < 2; i++)
#pragma unroll
        for (int j = 0; j < 4; j++)
#pragma unroll
            for (int v = 0; v < 4; v++) acc[i][j][v] = 0.0f;

    // precomputed store coordinates
    const int a_mt = ar >> 4, a_r = ar & 15;
    const int a_g = a_r & 7, a_hh = a_r >> 3;
    const int b_nt = br >> 3, b_g = br & 7;

    const int nch = klen / TBK;
    for (int ch = 0; ch < nch; ch++) {
        // ---- store prefetched registers to smem (with hi/lo split) ----
#pragma unroll
        for (int q = 0; q < 4; q++) {
            float v[4] = {afr[q].x, afr[q].y, afr[q].z, afr[q].w};
            int kbase = akb + q * 4;
            int ks = kbase >> 3;
            int slot = a_hh + (((kbase >> 2) & 1) << 1);
#pragma unroll
            for (int j = 0; j < 4; j++) {
                float hi = tf32_hi(v[j]);
                As[0][a_mt][ks][a_g * 4 + j][slot] = hi;
                As[1][a_mt][ks][a_g * 4 + j][slot] = v[j] - hi;
            }
        }
#pragma unroll
        for (int q = 0; q < 2; q++) {
            float v[4] = {bfr[q].x, bfr[q].y, bfr[q].z, bfr[q].w};
            int kbase = bkb + q * 4;
            int ks = kbase >> 3;
            int sh = (kbase >> 2) & 1;   // b0 / b1
#pragma unroll
            for (int j = 0; j < 4; j++) {
                float hi = tf32_hi(v[j]);
                Bs[b_nt][ks][b_g * 4 + j][sh]     = hi;
                Bs[b_nt][ks][b_g * 4 + j][sh + 2] = v[j] - hi;
            }
        }
        __syncthreads();

        // ---- prefetch next chunk (hidden behind compute) ----
        if (ch + 1 < nch) {
            Ag += TBK; Bg += TBK;
#pragma unroll
            for (int q = 0; q < 4; q++) afr[q] = *(const float4*)(Ag + q * 4);
#pragma unroll
            for (int q = 0; q < 2; q++) bfr[q] = *(const float4*)(Bg + q * 4);
        }

        // ---- mainloop over 4 k-steps of 8 ----
#pragma unroll
        for (int ks = 0; ks < NKS; ks++) {
            float4 ah[2], al[2], bb[4];
#pragma unroll
            for (int i = 0; i < 2; i++) {
                ah[i] = *(const float4*)&As[0][wm * 2 + i][ks][lane][0];
                al[i] = *(const float4*)&As[1][wm * 2 + i][ks][lane][0];
            }
#pragma unroll
            for (int j = 0; j < 4; j++)
                bb[j] = *(const float4*)&Bs[wn * 4 + j][ks][lane][0];

#pragma unroll
            for (int i = 0; i < 2; i++) {
                uint32_t ah0 = __float_as_uint(ah[i].x), ah1 = __float_as_uint(ah[i].y);
                uint32_t ah2 = __float_as_uint(ah[i].z), ah3 = __float_as_uint(ah[i].w);
                uint32_t al0 = __float_as_uint(al[i].x), al1 = __float_as_uint(al[i].y);
                uint32_t al2 = __float_as_uint(al[i].z), al3 = __float_as_uint(al[i].w);
#pragma unroll
                for (int j = 0; j < 4; j++) {
                    uint32_t bh0 = __float_as_uint(bb[j].x), bh1 = __float_as_uint(bb[j].y);
                    uint32_t bl0 = __float_as_uint(bb[j].z), bl1 = __float_as_uint(bb[j].w);
                    mma_tf32(acc[i][j], ah0, ah1, ah2, ah3, bh0, bh1); // hi*hi
                    mma_tf32(acc[i][j], al0, al1, al2, al3, bh0, bh1); // lo*hi
                    mma_tf32(acc[i][j], ah0, ah1, ah2, ah3, bl0, bl1); // hi*lo
                }
            }
        }
        __syncthreads();
    }

    // ---- epilogue ----
#pragma unroll
    for (int i = 0; i < 2; i++) {
#pragma unroll
        for (int j = 0; j < 4; j++) {
            int row = m0 + wm * 32 + i * 16 + (lane >> 2);
            int col = n0 + wn * 32 + j * 8 + (lane & 3) * 2;
            size_t o0 = (size_t)row * N + col;
            size_t o1 = (size_t)(row + 8) * N + col;
            if (ATOMIC) {
                atomicAdd(&C[o0],     acc[i][j][0]);
                atomicAdd(&C[o0 + 1], acc[i][j][1]);
                atomicAdd(&C[o1],     acc[i][j][2]);
                atomicAdd(&C[o1 + 1], acc[i][j][3]);
            } else {
                *(float2*)(C + o0) = make_float2(acc[i][j][0], acc[i][j][1]);
                *(float2*)(C + o1) = make_float2(acc[i][j][2], acc[i][j][3]);
            }
        }
    }
}

// ---------------------------------------------------------------------------
// Conv step
// ---------------------------------------------------------------------------
__global__ __launch_bounds__(256) void conv_kernel(
    const float* __restrict__ conv_in,
    const float* __restrict__ conv_w,
    const float* __restrict__ conv_b,
    float* __restrict__ conv_out)
{
    const int c = blockIdx.x * 256 + threadIdx.x;
    const int b = blockIdx.y;
    const size_t idx = (size_t)b * CONV_DIM + c;

    float4 s = *(const float4*)(conv_in + idx * 4);
    float4 w = *(const float4*)(conv_w + (size_t)c * 4);
    float xin = g_zxbcdt[(size_t)b * D_IN_PROJ + D_SSM + c];

    float v = s.y * w.x + s.z * w.y + s.w * w.z + xin * w.w + conv_b[c];
    float act = v / (1.0f + expf(-v));

    *(float4*)(conv_out + idx * 4) = make_float4(s.y, s.z, s.w, xin);
    g_act[idx] = act;
}

// ---------------------------------------------------------------------------
// SSM fused kernel (unchanged — 75% DRAM, near roofline)
// ---------------------------------------------------------------------------
__global__ __launch_bounds__(256) void ssm_kernel(
    const float* __restrict__ ssm_in,
    const float* __restrict__ dt_bias,
    const float* __restrict__ A_log,
    const float* __restrict__ Dvec,
    float* __restrict__ ssm_out)
{
    const int h = blockIdx.x;
    const int b = blockIdx.y;
    const int tid = threadIdx.x;

    __shared__ __align__(16) float sB[D_STATE];
    __shared__ __align__(16) float sC[D_STATE];
    __shared__ float s_dt, s_dA, s_Dh;

    if (tid == 0) {
        float v = g_zxbcdt[(size_t)b * D_IN_PROJ + (2 * D_SSM + 2 * D_STATE) + h]
                  + dt_bias[h];
        float dt = fmaxf(v, 0.0f) + log1pf(expf(-fabsf(v)));
        float A  = -expf(A_log[h]);
        s_dt = dt;
        s_dA = expf(dt * A);
        s_Dh = Dvec[h];
    }
    if (tid < D_STATE) {
        sB[tid] = g_act[(size_t)b * CONV_DIM + D_SSM + tid];
        sC[tid] = g_act[(size_t)b * CONV_DIM + D_SSM + D_STATE + tid];
    }
    __syncthreads();

    const float dt = s_dt, dA = s_dA, Dh = s_Dh;
    const int warp = tid >> 5, lane = tid & 31;

    const float* base_in  = ssm_in  + (((size_t)b * NHEADS + h) * HEADDIM) * D_STATE;
    float*       base_out = ssm_out + (((size_t)b * NHEADS + h) * HEADDIM) * D_STATE;

    const float4 bbv = *(const float4*)&sB[lane * 4];
    const float4 ccv = *(const float4*)&sC[lane * 4];

#pragma unroll
    for (int r = 0; r < 8; r++) {
        const int p = warp * 8 + r;
        float x = g_act[(size_t)b * CONV_DIM + h * HEADDIM + p];
        float xdt = x * dt;

        float4 st = *(const float4*)(base_in + (size_t)p * D_STATE + lane * 4);
        float n0 = st.x * dA + bbv.x * xdt;
        float n1 = st.y * dA + bbv.y * xdt;
        float n2 = st.z * dA + bbv.z * xdt;
        float n3 = st.w * dA + bbv.w * xdt;
        *(float4*)(base_out + (size_t)p * D_STATE + lane * 4) =
            make_float4(n0, n1, n2, n3);

        float ysum = n0 * ccv.x + n1 * ccv.y + n2 * ccv.z + n3 * ccv.w;
#pragma unroll
        for (int off = 16; off; off >>= 1)
            ysum += __shfl_xor_sync(0xffffffffu, ysum, off);

        if (lane == 0) {
            float y = ysum + Dh * x;
            float z = g_zxbcdt[(size_t)b * D_IN_PROJ + h * HEADDIM + p];
            float sz = z / (1.0f + expf(-z));
            g_yz[(size_t)b * D_SSM + h * HEADDIM + p] = y * sz;
        }
    }
}

__global__ void zero_kernel(float* __restrict__ p, int n) {
    int i = blockIdx.x * blockDim.x + threadIdx.x;
    if (i < n) p[i] = 0.0f;
}

// ---------------------------------------------------------------------------
// Launch
// ---------------------------------------------------------------------------
extern "C" void kernel_launch(void* const* d_in, const int* in_sizes, int n_in,
                              void* d_out, int out_size)
{
    const float* hidden    = (const float*)d_in[0];
    const float* conv_in   = (const float*)d_in[1];
    const float* ssm_in    = (const float*)d_in[2];
    const float* in_proj_w = (const float*)d_in[3];
    const float* conv_w    = (const float*)d_in[4];
    const float* conv_b    = (const float*)d_in[5];
    const float* dt_bias   = (const float*)d_in[6];
    const float* A_log     = (const float*)d_in[7];
    const float* Dvec      = (const float*)d_in[8];
    const float* out_w     = (const float*)d_in[9];

    float* out_p  = (float*)d_out;
    float* conv_p = out_p + OUT_N;
    float* ssm_p  = out_p + SSM_OFF;

    float* zx;  cudaGetSymbolAddress((void**)&zx, g_zxbcdt);
    float* yz;  cudaGetSymbolAddress((void**)&yz, g_yz);

    // 0) zero out-proj output region (split-K atomics accumulate into it)
    zero_kernel<<<(OUT_N + 255) / 256, 256>>>(out_p, OUT_N);

    // 1) in_proj: zxbcdt[256,8512] = hidden @ in_proj_w^T
    {
        dim3 grid(D_IN_PROJ / TBN, BATCH / TBM, 1);   // (133, 2, 1)
        gemm_tc<false><<<grid, 256>>>(hidden, in_proj_w, zx,
                                      BATCH, D_IN_PROJ, D_MODEL, D_MODEL);
    }

    // 2) conv step
    {
        dim3 grid(CONV_DIM / 256, BATCH, 1);
        conv_kernel<<<grid, 256>>>(conv_in, conv_w, conv_b, conv_p);
    }

    // 3) fused SSM update + y*silu(z)
    {
        dim3 grid(NHEADS, BATCH, 1);
        ssm_kernel<<<grid, 256>>>(ssm_in, dt_bias, A_log, Dvec, ssm_p);
    }

    // 4) out_proj: out[256,2048] = yz @ out_w^T   (split-K=4, atomic)
    {
        dim3 grid(D_MODEL / TBN, BATCH / TBM, 4);     // (32, 2, 4)
        gemm_tc<true><<<grid, 256>>>(yz, out_w, out_p,
                                     BATCH, D_MODEL, D_SSM, D_SSM / 4);
    }
}

// round 5
// speedup vs baseline: 1.8322x; 1.8322x over previous
#include <cuda_runtime.h>
#include <cuda_bf16.h>
#include <cstdint>

// ---------------------------------------------------------------------------
// Problem constants
// ---------------------------------------------------------------------------
#define BATCH     256
#define D_MODEL   2048
#define D_STATE   128
#define D_CONV    4
#define D_SSM     4096
#define NHEADS    64
#define HEADDIM   64
#define CONV_DIM  (D_SSM + 2 * D_STATE)              // 4352
#define D_IN_PROJ (2 * D_SSM + 2 * D_STATE + NHEADS) // 8512

#define OUT_N   (BATCH * D_MODEL)
#define CONV_N  (BATCH * CONV_DIM * D_CONV)
#define SSM_OFF (OUT_N + CONV_N)

// ---------------------------------------------------------------------------
// Scratch
// ---------------------------------------------------------------------------
__device__ float g_zxbcdt[(size_t)BATCH * D_IN_PROJ];
__device__ float g_act[(size_t)BATCH * CONV_DIM];
__device__ float g_yz[(size_t)BATCH * D_SSM];

// ---------------------------------------------------------------------------
// mma.sync bf16 + ldmatrix helpers (sm_80-era PTX -> valid on base sm_103)
// ---------------------------------------------------------------------------
__device__ __forceinline__ void ldsm4(uint32_t* r, uint32_t addr) {
    asm volatile("ldmatrix.sync.aligned.m8n8.x4.shared.b16 {%0,%1,%2,%3}, [%4];"
                 : "=r"(r[0]), "=r"(r[1]), "=r"(r[2]), "=r"(r[3]) : "r"(addr));
}

__device__ __forceinline__ void mma_bf16(float* d, const uint32_t* a,
                                         const uint32_t* b) {
    asm volatile(
        "mma.sync.aligned.m16n8k16.row.col.f32.bf16.bf16.f32 "
        "{%0,%1,%2,%3}, {%4,%5,%6,%7}, {%8,%9}, {%0,%1,%2,%3};"
        : "+f"(d[0]), "+f"(d[1]), "+f"(d[2]), "+f"(d[3])
        : "r"(a[0]), "r"(a[1]), "r"(a[2]), "r"(a[3]), "r"(b[0]), "r"(b[1]));
}

__device__ __forceinline__ uint32_t smem_u32(const void* p) {
    uint32_t a;
    asm("{ .reg .u64 t; cvta.to.shared.u64 t, %1; cvt.u32.u64 %0, t; }"
        : "=r"(a) : "l"(p));
    return a;
}

// 8 consecutive floats -> hi bf16x4 word-pair + lo bf16x4 word-pair (16B each)
__device__ __forceinline__ void split8(const float4& p0, const float4& p1,
                                       uint4& hi, uint4& lo)
{
    float f[8] = {p0.x, p0.y, p0.z, p0.w, p1.x, p1.y, p1.z, p1.w};
    uint32_t h[4], l[4];
#pragma unroll
    for (int i = 0; i < 4; i++) {
        uint32_t w;
        asm("cvt.rn.bf16x2.f32 %0, %1, %2;" : "=r"(w) : "f"(f[2*i+1]), "f"(f[2*i]));
        float h0 = __uint_as_float(w << 16);
        float h1 = __uint_as_float(w & 0xffff0000u);
        float l0 = f[2*i]   - h0;
        float l1 = f[2*i+1] - h1;
        uint32_t wl;
        asm("cvt.rn.bf16x2.f32 %0, %1, %2;" : "=r"(wl) : "f"(l1), "f"(l0));
        h[i] = w; l[i] = wl;
    }
    hi = make_uint4(h[0], h[1], h[2], h[3]);
    lo = make_uint4(l[0], l[1], l[2], l[3]);
}

#define SW128(bo) ((bo) ^ (((bo) >> 3) & 0x70))

// ---------------------------------------------------------------------------
// bf16 tensor-core GEMM (3-term split): C[M,N] = A[M,K] @ B[N,K]^T, fp32 io.
// Block tile 128x64, BK=64 (one SW128 row). 256 thr, 8 warps 4x2, 32x32/warp.
// smem: Ahi 16K | Alo 16K | Bhi 8K | Blo 8K = 48 KB (single buf, reg prefetch)
// ---------------------------------------------------------------------------
#define BKC 64
#define SA_HI 0
#define SA_LO 16384
#define SB_HI 32768
#define SB_LO 40960

template <bool ATOMIC>
__global__ __launch_bounds__(256) void gemm_bf16_tc(
    const float* __restrict__ A, const float* __restrict__ B,
    float* __restrict__ C, int M, int N, int K, int klen)
{
    __shared__ __align__(1024) char sm[49152];
    const uint32_t sb = smem_u32(sm);

    const int tid  = threadIdx.x;
    const int lane = tid & 31;
    const int warp = tid >> 5;
    const int n0 = blockIdx.x * 64;
    const int m0 = blockIdx.y * 128;
    const int k0 = blockIdx.z * klen;
    const int wm = warp >> 1;      // 0..3
    const int wn = warp & 1;       // 0..1

    // ---- global load mapping (per 128x64 / 64x64 chunk) ----
    const int a_r  = tid >> 1;          // 0..127
    const int a_kb = (tid & 1) * 32;    // 0 / 32
    const int b_r  = tid >> 2;          // 0..63
    const int b_kb = (tid & 3) * 16;    // 0..48

    const float* Ag = A + (size_t)(m0 + a_r) * K + k0 + a_kb;
    const float* Bg = B + (size_t)(n0 + b_r) * K + k0 + b_kb;

    // pre-swizzled smem store offsets (16B granules)
    uint32_t a_sw[4], b_sw[2];
#pragma unroll
    for (int g = 0; g < 4; g++) {
        uint32_t bo = a_r * 128 + (a_kb + 8 * g) * 2;
        a_sw[g] = SW128(bo);
    }
#pragma unroll
    for (int g = 0; g < 2; g++) {
        uint32_t bo = b_r * 128 + (b_kb + 8 * g) * 2;
        b_sw[g] = SW128(bo);
    }

    // ---- ldmatrix lane addressing (row part constant per thread) ----
    const int g4 = lane >> 3;                         // 0..3
    const int ra = wm * 32 + ((g4 & 1) << 3) + (lane & 7);
    const uint32_t a_xm   = (uint32_t)(ra & 7) << 4;
    const uint32_t a_base = sb + SA_HI + ra * 128;
    const uint32_t a_koff = (uint32_t)(g4 >> 1) << 4;

    const int rb = wn * 32 + ((g4 >> 1) << 3) + (lane & 7);
    const uint32_t b_xm   = (uint32_t)(rb & 7) << 4;
    const uint32_t b_base = sb + SB_HI + rb * 128;
    const uint32_t b_koff = (uint32_t)(g4 & 1) << 4;

    // ---- prefetch chunk 0 ----
    float4 av[8], bv[4];
#pragma unroll
    for (int q = 0; q < 8; q++) av[q] = *(const float4*)(Ag + q * 4);
#pragma unroll
    for (int q = 0; q < 4; q++) bv[q] = *(const float4*)(Bg + q * 4);

    float acc[2][4][4];
#pragma unroll
    for (int i = 0; i < 2; i++)
#pragma unroll
        for (int j = 0; j < 4; j++)
#pragma unroll
            for (int v = 0; v < 4; v++) acc[i][j][v] = 0.0f;

    const int nch = klen / BKC;
    for (int c = 0; c < nch; c++) {
        // ---- convert + store current chunk ----
#pragma unroll
        for (int g = 0; g < 4; g++) {
            uint4 hi, lo; split8(av[2*g], av[2*g+1], hi, lo);
            *(uint4*)(sm + SA_HI + a_sw[g]) = hi;
            *(uint4*)(sm + SA_LO + a_sw[g]) = lo;
        }
#pragma unroll
        for (int g = 0; g < 2; g++) {
            uint4 hi, lo; split8(bv[2*g], bv[2*g+1], hi, lo);
            *(uint4*)(sm + SB_HI + b_sw[g]) = hi;
            *(uint4*)(sm + SB_LO + b_sw[g]) = lo;
        }
        __syncthreads();

        // ---- prefetch next chunk (LDG latency hidden under MMA phase) ----
        if (c + 1 < nch) {
            Ag += BKC; Bg += BKC;
#pragma unroll
            for (int q = 0; q < 8; q++) av[q] = *(const float4*)(Ag + q * 4);
#pragma unroll
            for (int q = 0; q < 4; q++) bv[q] = *(const float4*)(Bg + q * 4);
        }

        // ---- compute: 4 k16 steps ----
#pragma unroll
        for (int ks = 0; ks < 4; ks++) {
            uint32_t ah[2][4], al[2][4], bh[2][4], bl[2][4];
            const uint32_t ak = ((uint32_t)(32 * ks) | a_koff) ^ a_xm;
            const uint32_t bk = ((uint32_t)(32 * ks) | b_koff) ^ b_xm;
#pragma unroll
            for (int i = 0; i < 2; i++) {
                uint32_t ad = a_base + i * 2048 + ak;
                ldsm4(ah[i], ad);
                ldsm4(al[i], ad + (SA_LO - SA_HI));
            }
#pragma unroll
            for (int jj = 0; jj < 2; jj++) {
                uint32_t bd = b_base + jj * 2048 + bk;
                ldsm4(bh[jj], bd);
                ldsm4(bl[jj], bd + (SB_LO - SB_HI));
            }
#pragma unroll
            for (int i = 0; i < 2; i++) {
#pragma unroll
                for (int j = 0; j < 4; j++) {
                    const uint32_t* Bh = &bh[j >> 1][(j & 1) * 2];
                    const uint32_t* Bl = &bl[j >> 1][(j & 1) * 2];
                    mma_bf16(acc[i][j], ah[i], Bh);   // hi*hi
                    mma_bf16(acc[i][j], al[i], Bh);   // lo*hi
                    mma_bf16(acc[i][j], ah[i], Bl);   // hi*lo
                }
            }
        }
        __syncthreads();
    }

    // ---- epilogue ----
#pragma unroll
    for (int i = 0; i < 2; i++) {
#pragma unroll
        for (int j = 0; j < 4; j++) {
            int row = m0 + wm * 32 + i * 16 + (lane >> 2);
            int col = n0 + wn * 32 + j * 8 + (lane & 3) * 2;
            size_t o0 = (size_t)row * N + col;
            size_t o1 = (size_t)(row + 8) * N + col;
            if (ATOMIC) {
                atomicAdd(&C[o0],     acc[i][j][0]);
                atomicAdd(&C[o0 + 1], acc[i][j][1]);
                atomicAdd(&C[o1],     acc[i][j][2]);
                atomicAdd(&C[o1 + 1], acc[i][j][3]);
            } else {
                *(float2*)(C + o0) = make_float2(acc[i][j][0], acc[i][j][1]);
                *(float2*)(C + o1) = make_float2(acc[i][j][2], acc[i][j][3]);
            }
        }
    }
}

// ---------------------------------------------------------------------------
// Conv step
// ---------------------------------------------------------------------------
__global__ __launch_bounds__(256) void conv_kernel(
    const float* __restrict__ conv_in,
    const float* __restrict__ conv_w,
    const float* __restrict__ conv_b,
    float* __restrict__ conv_out)
{
    const int c = blockIdx.x * 256 + threadIdx.x;
    const int b = blockIdx.y;
    const size_t idx = (size_t)b * CONV_DIM + c;

    float4 s = *(const float4*)(conv_in + idx * 4);
    float4 w = *(const float4*)(conv_w + (size_t)c * 4);
    float xin = g_zxbcdt[(size_t)b * D_IN_PROJ + D_SSM + c];

    float v = s.y * w.x + s.z * w.y + s.w * w.z + xin * w.w + conv_b[c];
    float act = v / (1.0f + expf(-v));

    *(float4*)(conv_out + idx * 4) = make_float4(s.y, s.z, s.w, xin);
    g_act[idx] = act;
}

// ---------------------------------------------------------------------------
// SSM fused kernel — state-load software pipeline (MLP 1 -> 2)
// ---------------------------------------------------------------------------
__global__ __launch_bounds__(256) void ssm_kernel(
    const float* __restrict__ ssm_in,
    const float* __restrict__ dt_bias,
    const float* __restrict__ A_log,
    const float* __restrict__ Dvec,
    float* __restrict__ ssm_out)
{
    const int h = blockIdx.x;
    const int b = blockIdx.y;
    const int tid = threadIdx.x;

    __shared__ __align__(16) float sB[D_STATE];
    __shared__ __align__(16) float sC[D_STATE];
    __shared__ float s_dt, s_dA, s_Dh;

    if (tid == 0) {
        float v = g_zxbcdt[(size_t)b * D_IN_PROJ + (2 * D_SSM + 2 * D_STATE) + h]
                  + dt_bias[h];
        float dt = fmaxf(v, 0.0f) + log1pf(expf(-fabsf(v)));
        float A  = -expf(A_log[h]);
        s_dt = dt;
        s_dA = expf(dt * A);
        s_Dh = Dvec[h];
    }
    if (tid < D_STATE) {
        sB[tid] = g_act[(size_t)b * CONV_DIM + D_SSM + tid];
        sC[tid] = g_act[(size_t)b * CONV_DIM + D_SSM + D_STATE + tid];
    }
    __syncthreads();

    const float dt = s_dt, dA = s_dA, Dh = s_Dh;
    const int warp = tid >> 5, lane = tid & 31;

    const float* base_in  = ssm_in  + (((size_t)b * NHEADS + h) * HEADDIM) * D_STATE;
    float*       base_out = ssm_out + (((size_t)b * NHEADS + h) * HEADDIM) * D_STATE;

    const float4 bbv = *(const float4*)&sB[lane * 4];
    const float4 ccv = *(const float4*)&sC[lane * 4];

    float4 st = *(const float4*)(base_in + (size_t)(warp * 8) * D_STATE + lane * 4);

#pragma unroll
    for (int r = 0; r < 8; r++) {
        const int p = warp * 8 + r;
        float4 st_next;
        if (r < 7)
            st_next = *(const float4*)(base_in + (size_t)(p + 1) * D_STATE + lane * 4);

        float x = g_act[(size_t)b * CONV_DIM + h * HEADDIM + p];
        float xdt = x * dt;

        float n0 = st.x * dA + bbv.x * xdt;
        float n1 = st.y * dA + bbv.y * xdt;
        float n2 = st.z * dA + bbv.z * xdt;
        float n3 = st.w * dA + bbv.w * xdt;
        *(float4*)(base_out + (size_t)p * D_STATE + lane * 4) =
            make_float4(n0, n1, n2, n3);

        float ysum = n0 * ccv.x + n1 * ccv.y + n2 * ccv.z + n3 * ccv.w;
#pragma unroll
        for (int off = 16; off; off >>= 1)
            ysum += __shfl_xor_sync(0xffffffffu, ysum, off);

        if (lane == 0) {
            float y = ysum + Dh * x;
            float z = g_zxbcdt[(size_t)b * D_IN_PROJ + h * HEADDIM + p];
            float sz = z / (1.0f + expf(-z));
            g_yz[(size_t)b * D_SSM + h * HEADDIM + p] = y * sz;
        }
        st = st_next;
    }
}

__global__ void zero_kernel(float* __restrict__ p, int n) {
    int i = blockIdx.x * blockDim.x + threadIdx.x;
    if (i < n) p[i] = 0.0f;
}

// ---------------------------------------------------------------------------
// Launch
// ---------------------------------------------------------------------------
extern "C" void kernel_launch(void* const* d_in, const int* in_sizes, int n_in,
                              void* d_out, int out_size)
{
    const float* hidden    = (const float*)d_in[0];
    const float* conv_in   = (const float*)d_in[1];
    const float* ssm_in    = (const float*)d_in[2];
    const float* in_proj_w = (const float*)d_in[3];
    const float* conv_w    = (const float*)d_in[4];
    const float* conv_b    = (const float*)d_in[5];
    const float* dt_bias   = (const float*)d_in[6];
    const float* A_log     = (const float*)d_in[7];
    const float* Dvec      = (const float*)d_in[8];
    const float* out_w     = (const float*)d_in[9];

    float* out_p  = (float*)d_out;
    float* conv_p = out_p + OUT_N;
    float* ssm_p  = out_p + SSM_OFF;

    float* zx;  cudaGetSymbolAddress((void**)&zx, g_zxbcdt);
    float* yz;  cudaGetSymbolAddress((void**)&yz, g_yz);

    // 0) zero out-proj output region (split-K atomics accumulate into it)
    zero_kernel<<<(OUT_N + 255) / 256, 256>>>(out_p, OUT_N);

    // 1) in_proj: zxbcdt[256,8512] = hidden @ in_proj_w^T
    {
        dim3 grid(D_IN_PROJ / 64, BATCH / 128, 1);    // (133, 2, 1)
        gemm_bf16_tc<false><<<grid, 256>>>(hidden, in_proj_w, zx,
                                           BATCH, D_IN_PROJ, D_MODEL, D_MODEL);
    }

    // 2) conv step
    {
        dim3 grid(CONV_DIM / 256, BATCH, 1);
        conv_kernel<<<grid, 256>>>(conv_in, conv_w, conv_b, conv_p);
    }

    // 3) fused SSM update + y*silu(z)
    {
        dim3 grid(NHEADS, BATCH, 1);
        ssm_kernel<<<grid, 256>>>(ssm_in, dt_bias, A_log, Dvec, ssm_p);
    }

    // 4) out_proj: out[256,2048] = yz @ out_w^T   (split-K=4, atomic)
    {
        dim3 grid(D_MODEL / 64, BATCH / 128, 4);      // (32, 2, 4)
        gemm_bf16_tc<true><<<grid, 256>>>(yz, out_w, out_p,
                                          BATCH, D_MODEL, D_SSM, D_SSM / 4);
    }
}

// round 6
// speedup vs baseline: 2.2681x; 1.2379x over previous
#include <cuda_runtime.h>
#include <cuda_bf16.h>
#include <cstdint>

// ---------------------------------------------------------------------------
// Problem constants
// ---------------------------------------------------------------------------
#define BATCH     256
#define D_MODEL   2048
#define D_STATE   128
#define D_CONV    4
#define D_SSM     4096
#define NHEADS    64
#define HEADDIM   64
#define CONV_DIM  (D_SSM + 2 * D_STATE)              // 4352
#define D_IN_PROJ (2 * D_SSM + 2 * D_STATE + NHEADS) // 8512

#define OUT_N   (BATCH * D_MODEL)
#define CONV_N  (BATCH * CONV_DIM * D_CONV)
#define SSM_OFF (OUT_N + CONV_N)

// ---------------------------------------------------------------------------
// Scratch (__device__ globals — no allocation allowed)
// ---------------------------------------------------------------------------
__device__ float g_zxbcdt[(size_t)BATCH * D_IN_PROJ];
__device__ float g_act[(size_t)BATCH * CONV_DIM];

// bf16 hi/lo pre-split operands
__device__ __nv_bfloat16 g_ip_hi[(size_t)D_IN_PROJ * D_MODEL];
__device__ __nv_bfloat16 g_ip_lo[(size_t)D_IN_PROJ * D_MODEL];
__device__ __nv_bfloat16 g_op_hi[(size_t)D_MODEL * D_SSM];
__device__ __nv_bfloat16 g_op_lo[(size_t)D_MODEL * D_SSM];
__device__ __nv_bfloat16 g_h_hi[(size_t)BATCH * D_MODEL];
__device__ __nv_bfloat16 g_h_lo[(size_t)BATCH * D_MODEL];
__device__ __nv_bfloat16 g_yz_hi[(size_t)BATCH * D_SSM];
__device__ __nv_bfloat16 g_yz_lo[(size_t)BATCH * D_SSM];

// ---------------------------------------------------------------------------
// PTX helpers
// ---------------------------------------------------------------------------
__device__ __forceinline__ void ldsm4(uint32_t* r, uint32_t addr) {
    asm volatile("ldmatrix.sync.aligned.m8n8.x4.shared.b16 {%0,%1,%2,%3}, [%4];"
                 : "=r"(r[0]), "=r"(r[1]), "=r"(r[2]), "=r"(r[3]) : "r"(addr));
}

__device__ __forceinline__ void mma_bf16(float* d, const uint32_t* a,
                                         const uint32_t* b) {
    asm volatile(
        "mma.sync.aligned.m16n8k16.row.col.f32.bf16.bf16.f32 "
        "{%0,%1,%2,%3}, {%4,%5,%6,%7}, {%8,%9}, {%0,%1,%2,%3};"
        : "+f"(d[0]), "+f"(d[1]), "+f"(d[2]), "+f"(d[3])
        : "r"(a[0]), "r"(a[1]), "r"(a[2]), "r"(a[3]), "r"(b[0]), "r"(b[1]));
}

__device__ __forceinline__ uint32_t smem_u32(const void* p) {
    uint32_t a;
    asm("{ .reg .u64 t; cvta.to.shared.u64 t, %1; cvt.u32.u64 %0, t; }"
        : "=r"(a) : "l"(p));
    return a;
}

__device__ __forceinline__ void cpasync16(uint32_t dst, const void* src) {
    asm volatile("cp.async.cg.shared.global [%0], [%1], 16;"
                 :: "r"(dst), "l"(src));
}
#define CP_COMMIT() asm volatile("cp.async.commit_group;" ::: "memory")
#define CP_WAIT(n)  asm volatile("cp.async.wait_group %0;" :: "n"(n) : "memory")

#define SW128(bo) ((bo) ^ (((bo) >> 3) & 0x70))

// 4 floats -> hi bf16x2-pair + lo bf16x2-pair
__device__ __forceinline__ void split4(const float4& v, uint2& hi, uint2& lo) {
    float f[4] = {v.x, v.y, v.z, v.w};
    uint32_t h[2], l[2];
#pragma unroll
    for (int i = 0; i < 2; i++) {
        uint32_t w;
        asm("cvt.rn.bf16x2.f32 %0, %1, %2;" : "=r"(w) : "f"(f[2*i+1]), "f"(f[2*i]));
        float h0 = __uint_as_float(w << 16);
        float h1 = __uint_as_float(w & 0xffff0000u);
        float l0 = f[2*i]   - h0;
        float l1 = f[2*i+1] - h1;
        uint32_t wl;
        asm("cvt.rn.bf16x2.f32 %0, %1, %2;" : "=r"(wl) : "f"(l1), "f"(l0));
        h[i] = w; l[i] = wl;
    }
    hi = make_uint2(h[0], h[1]);
    lo = make_uint2(l[0], l[1]);
}

// ---------------------------------------------------------------------------
// fp32 -> bf16 hi/lo split kernel (vectorized float4)
// ---------------------------------------------------------------------------
__global__ __launch_bounds__(256) void split_kernel(
    const float4* __restrict__ in, uint2* __restrict__ hi,
    uint2* __restrict__ lo, int n4)
{
    int i = blockIdx.x * 256 + threadIdx.x;
    if (i >= n4) return;
    uint2 h, l;
    split4(in[i], h, l);
    hi[i] = h;
    lo[i] = l;
}

// ---------------------------------------------------------------------------
// bf16 tensor-core GEMM (3-term split), cp.async 2-stage pipeline.
// C[M,N] = A[M,K] @ B[N,K]^T; A,B given as pre-split bf16 hi/lo (K-major).
// Block tile 128x64, BK=64 elems (one SW128 row). 256 thr, 8 warps (4x2).
// Stage: Ahi 16K | Alo 16K | Bhi 8K | Blo 8K = 48 KB; 2 stages = 96 KB dyn.
// ---------------------------------------------------------------------------
#define BKC 64
#define STG 49152
#define ST_AHI 0
#define ST_ALO 16384
#define ST_BHI 32768
#define ST_BLO 40960
#define GEMM_SMEM (2 * STG)

template <bool ATOMIC>
__global__ __launch_bounds__(256) void gemm_bf16_tc(
    const __nv_bfloat16* __restrict__ Ahi, const __nv_bfloat16* __restrict__ Alo,
    const __nv_bfloat16* __restrict__ Bhi, const __nv_bfloat16* __restrict__ Blo,
    float* __restrict__ C, int M, int N, int K, int klen)
{
    extern __shared__ __align__(1024) char sm[];
    const uint32_t sb = smem_u32(sm);

    const int tid  = threadIdx.x;
    const int lane = tid & 31;
    const int warp = tid >> 5;
    const int n0 = blockIdx.x * 64;
    const int m0 = blockIdx.y * 128;
    const int k0 = blockIdx.z * klen;
    const int wm = warp >> 1;      // 0..3
    const int wn = warp & 1;       // 0..1

    // ---- async-copy mapping ----
    // A: 128 rows x 8 granules(16B) = 1024 granules -> 4 per thread
    // B:  64 rows x 8 granules      =  512 granules -> 2 per thread
    uint32_t a_sw[4], b_sw[2];
    const __nv_bfloat16 *a_src[4], *b_src[2];
#pragma unroll
    for (int t = 0; t < 4; t++) {
        int idx = tid + t * 256;
        int r = idx >> 3, g = idx & 7;
        a_sw[t] = SW128((uint32_t)(r * 128 + g * 16));
        a_src[t] = Ahi + (size_t)(m0 + r) * K + k0 + g * 8;
    }
#pragma unroll
    for (int t = 0; t < 2; t++) {
        int idx = tid + t * 256;
        int r = idx >> 3, g = idx & 7;
        b_sw[t] = SW128((uint32_t)(r * 128 + g * 16));
        b_src[t] = Bhi + (size_t)(n0 + r) * K + k0 + g * 8;
    }
    const ptrdiff_t dAL = Alo - Ahi;   // element offset between hi and lo arrays
    const ptrdiff_t dBL = Blo - Bhi;

    // ---- ldmatrix lane addressing ----
    const int g4 = lane >> 3;
    const int ra = wm * 32 + ((g4 & 1) << 3) + (lane & 7);
    const uint32_t a_xm   = (uint32_t)(ra & 7) << 4;
    const uint32_t a_row  = (uint32_t)(ra * 128);
    const uint32_t a_koff = (uint32_t)(g4 >> 1) << 4;

    const int rb = wn * 32 + ((g4 >> 1) << 3) + (lane & 7);
    const uint32_t b_xm   = (uint32_t)(rb & 7) << 4;
    const uint32_t b_row  = (uint32_t)(rb * 128);
    const uint32_t b_koff = (uint32_t)(g4 & 1) << 4;

    float acc[2][4][4];
#pragma unroll
    for (int i = 0; i < 2; i++)
#pragma unroll
        for (int j = 0; j < 4; j++)
#pragma unroll
            for (int v = 0; v < 4; v++) acc[i][j][v] = 0.0f;

    const int nch = klen / BKC;

    // issue stage 0
    {
        const uint32_t s0 = sb;
#pragma unroll
        for (int t = 0; t < 4; t++) {
            cpasync16(s0 + ST_AHI + a_sw[t], a_src[t]);
            cpasync16(s0 + ST_ALO + a_sw[t], a_src[t] + dAL);
        }
#pragma unroll
        for (int t = 0; t < 2; t++) {
            cpasync16(s0 + ST_BHI + b_sw[t], b_src[t]);
            cpasync16(s0 + ST_BLO + b_sw[t], b_src[t] + dBL);
        }
        CP_COMMIT();
    }

    for (int c = 0; c < nch; c++) {
        if (c + 1 < nch) {
            const uint32_t sn = sb + ((c + 1) & 1) * STG;
            const int koff = (c + 1) * BKC;
#pragma unroll
            for (int t = 0; t < 4; t++) {
                cpasync16(sn + ST_AHI + a_sw[t], a_src[t] + koff);
                cpasync16(sn + ST_ALO + a_sw[t], a_src[t] + koff + dAL);
            }
#pragma unroll
            for (int t = 0; t < 2; t++) {
                cpasync16(sn + ST_BHI + b_sw[t], b_src[t] + koff);
                cpasync16(sn + ST_BLO + b_sw[t], b_src[t] + koff + dBL);
            }
            CP_COMMIT();
            CP_WAIT(1);
        } else {
            CP_WAIT(0);
        }
        __syncthreads();

        const uint32_t ss = sb + (c & 1) * STG;
        const uint32_t a_base = ss + ST_AHI + a_row;
        const uint32_t b_base = ss + ST_BHI + b_row;

#pragma unroll
        for (int ks = 0; ks < 4; ks++) {
            uint32_t ah[2][4], al[2][4], bh[2][4], bl[2][4];
            const uint32_t ak = ((uint32_t)(32 * ks) | a_koff) ^ a_xm;
            const uint32_t bk = ((uint32_t)(32 * ks) | b_koff) ^ b_xm;
#pragma unroll
            for (int i = 0; i < 2; i++) {
                uint32_t ad = a_base + i * 2048 + ak;
                ldsm4(ah[i], ad);
                ldsm4(al[i], ad + (ST_ALO - ST_AHI));
            }
#pragma unroll
            for (int jj = 0; jj < 2; jj++) {
                uint32_t bd = b_base + jj * 2048 + bk;
                ldsm4(bh[jj], bd);
                ldsm4(bl[jj], bd + (ST_BLO - ST_BHI));
            }
#pragma unroll
            for (int i = 0; i < 2; i++) {
#pragma unroll
                for (int j = 0; j < 4; j++) {
                    const uint32_t* Bh = &bh[j >> 1][(j & 1) * 2];
                    const uint32_t* Bl = &bl[j >> 1][(j & 1) * 2];
                    mma_bf16(acc[i][j], ah[i], Bh);   // hi*hi
                    mma_bf16(acc[i][j], al[i], Bh);   // lo*hi
                    mma_bf16(acc[i][j], ah[i], Bl);   // hi*lo
                }
            }
        }
        __syncthreads();
    }

    // ---- epilogue ----
#pragma unroll
    for (int i = 0; i < 2; i++) {
#pragma unroll
        for (int j = 0; j < 4; j++) {
            int row = m0 + wm * 32 + i * 16 + (lane >> 2);
            int col = n0 + wn * 32 + j * 8 + (lane & 3) * 2;
            size_t o0 = (size_t)row * N + col;
            size_t o1 = (size_t)(row + 8) * N + col;
            if (ATOMIC) {
                atomicAdd(&C[o0],     acc[i][j][0]);
                atomicAdd(&C[o0 + 1], acc[i][j][1]);
                atomicAdd(&C[o1],     acc[i][j][2]);
                atomicAdd(&C[o1 + 1], acc[i][j][3]);
            } else {
                *(float2*)(C + o0) = make_float2(acc[i][j][0], acc[i][j][1]);
                *(float2*)(C + o1) = make_float2(acc[i][j][2], acc[i][j][3]);
            }
        }
    }
}

// ---------------------------------------------------------------------------
// Conv step
// ---------------------------------------------------------------------------
__global__ __launch_bounds__(256) void conv_kernel(
    const float* __restrict__ conv_in,
    const float* __restrict__ conv_w,
    const float* __restrict__ conv_b,
    float* __restrict__ conv_out)
{
    const int c = blockIdx.x * 256 + threadIdx.x;
    const int b = blockIdx.y;
    const size_t idx = (size_t)b * CONV_DIM + c;

    float4 s = *(const float4*)(conv_in + idx * 4);
    float4 w = *(const float4*)(conv_w + (size_t)c * 4);
    float xin = g_zxbcdt[(size_t)b * D_IN_PROJ + D_SSM + c];

    float v = s.y * w.x + s.z * w.y + s.w * w.z + xin * w.w + conv_b[c];
    float act = v / (1.0f + expf(-v));

    *(float4*)(conv_out + idx * 4) = make_float4(s.y, s.z, s.w, xin);
    g_act[idx] = act;
}

// ---------------------------------------------------------------------------
// SSM fused kernel — writes yz directly as bf16 hi/lo for out_proj
// ---------------------------------------------------------------------------
__global__ __launch_bounds__(256) void ssm_kernel(
    const float* __restrict__ ssm_in,
    const float* __restrict__ dt_bias,
    const float* __restrict__ A_log,
    const float* __restrict__ Dvec,
    float* __restrict__ ssm_out)
{
    const int h = blockIdx.x;
    const int b = blockIdx.y;
    const int tid = threadIdx.x;

    __shared__ __align__(16) float sB[D_STATE];
    __shared__ __align__(16) float sC[D_STATE];
    __shared__ float s_dt, s_dA, s_Dh;

    if (tid == 0) {
        float v = g_zxbcdt[(size_t)b * D_IN_PROJ + (2 * D_SSM + 2 * D_STATE) + h]
                  + dt_bias[h];
        float dt = fmaxf(v, 0.0f) + log1pf(expf(-fabsf(v)));
        float A  = -expf(A_log[h]);
        s_dt = dt;
        s_dA = expf(dt * A);
        s_Dh = Dvec[h];
    }
    if (tid < D_STATE) {
        sB[tid] = g_act[(size_t)b * CONV_DIM + D_SSM + tid];
        sC[tid] = g_act[(size_t)b * CONV_DIM + D_SSM + D_STATE + tid];
    }
    __syncthreads();

    const float dt = s_dt, dA = s_dA, Dh = s_Dh;
    const int warp = tid >> 5, lane = tid & 31;

    const float* base_in  = ssm_in  + (((size_t)b * NHEADS + h) * HEADDIM) * D_STATE;
    float*       base_out = ssm_out + (((size_t)b * NHEADS + h) * HEADDIM) * D_STATE;

    const float4 bbv = *(const float4*)&sB[lane * 4];
    const float4 ccv = *(const float4*)&sC[lane * 4];

#pragma unroll
    for (int r = 0; r < 8; r++) {
        const int p = warp * 8 + r;
        float x = g_act[(size_t)b * CONV_DIM + h * HEADDIM + p];
        float xdt = x * dt;

        float4 st = *(const float4*)(base_in + (size_t)p * D_STATE + lane * 4);
        float n0 = st.x * dA + bbv.x * xdt;
        float n1 = st.y * dA + bbv.y * xdt;
        float n2 = st.z * dA + bbv.z * xdt;
        float n3 = st.w * dA + bbv.w * xdt;
        *(float4*)(base_out + (size_t)p * D_STATE + lane * 4) =
            make_float4(n0, n1, n2, n3);

        float ysum = n0 * ccv.x + n1 * ccv.y + n2 * ccv.z + n3 * ccv.w;
#pragma unroll
        for (int off = 16; off; off >>= 1)
            ysum += __shfl_xor_sync(0xffffffffu, ysum, off);

        if (lane == 0) {
            float y = ysum + Dh * x;
            float z = g_zxbcdt[(size_t)b * D_IN_PROJ + h * HEADDIM + p];
            float sz = z / (1.0f + expf(-z));
            float yz = y * sz;
            size_t oy = (size_t)b * D_SSM + h * HEADDIM + p;
            __nv_bfloat16 hb = __float2bfloat16(yz);
            float hf = __bfloat162float(hb);
            g_yz_hi[oy] = hb;
            g_yz_lo[oy] = __float2bfloat16(yz - hf);
        }
    }
}

__global__ void zero_kernel(float* __restrict__ p, int n) {
    int i = blockIdx.x * blockDim.x + threadIdx.x;
    if (i < n) p[i] = 0.0f;
}

// ---------------------------------------------------------------------------
// Launch
// ---------------------------------------------------------------------------
extern "C" void kernel_launch(void* const* d_in, const int* in_sizes, int n_in,
                              void* d_out, int out_size)
{
    const float* hidden    = (const float*)d_in[0];
    const float* conv_in   = (const float*)d_in[1];
    const float* ssm_in    = (const float*)d_in[2];
    const float* in_proj_w = (const float*)d_in[3];
    const float* conv_w    = (const float*)d_in[4];
    const float* conv_b    = (const float*)d_in[5];
    const float* dt_bias   = (const float*)d_in[6];
    const float* A_log     = (const float*)d_in[7];
    const float* Dvec      = (const float*)d_in[8];
    const float* out_w     = (const float*)d_in[9];

    float* out_p  = (float*)d_out;
    float* conv_p = out_p + OUT_N;
    float* ssm_p  = out_p + SSM_OFF;

    float* zx; cudaGetSymbolAddress((void**)&zx, g_zxbcdt);
    __nv_bfloat16 *ip_hi, *ip_lo, *op_hi, *op_lo, *h_hi, *h_lo, *yz_hi, *yz_lo;
    cudaGetSymbolAddress((void**)&ip_hi, g_ip_hi);
    cudaGetSymbolAddress((void**)&ip_lo, g_ip_lo);
    cudaGetSymbolAddress((void**)&op_hi, g_op_hi);
    cudaGetSymbolAddress((void**)&op_lo, g_op_lo);
    cudaGetSymbolAddress((void**)&h_hi, g_h_hi);
    cudaGetSymbolAddress((void**)&h_lo, g_h_lo);
    cudaGetSymbolAddress((void**)&yz_hi, g_yz_hi);
    cudaGetSymbolAddress((void**)&yz_lo, g_yz_lo);

    static bool attr_set = false;
    if (!attr_set) {
        cudaFuncSetAttribute(gemm_bf16_tc<false>,
            cudaFuncAttributeMaxDynamicSharedMemorySize, GEMM_SMEM);
        cudaFuncSetAttribute(gemm_bf16_tc<true>,
            cudaFuncAttributeMaxDynamicSharedMemorySize, GEMM_SMEM);
        attr_set = true;
    }

    // 0) zero out-proj output region (split-K atomics accumulate into it)
    zero_kernel<<<(OUT_N + 255) / 256, 256>>>(out_p, OUT_N);

    // 0b) pre-split operands to bf16 hi/lo
    {
        int n4 = BATCH * D_MODEL / 4;
        split_kernel<<<(n4 + 255) / 256, 256>>>(
            (const float4*)hidden, (uint2*)h_hi, (uint2*)h_lo, n4);
    }
    {
        int n4 = D_IN_PROJ * D_MODEL / 4;
        split_kernel<<<(n4 + 255) / 256, 256>>>(
            (const float4*)in_proj_w, (uint2*)ip_hi, (uint2*)ip_lo, n4);
    }
    {
        int n4 = D_MODEL * D_SSM / 4;
        split_kernel<<<(n4 + 255) / 256, 256>>>(
            (const float4*)out_w, (uint2*)op_hi, (uint2*)op_lo, n4);
    }

    // 1) in_proj: zxbcdt[256,8512] = hidden @ in_proj_w^T
    {
        dim3 grid(D_IN_PROJ / 64, BATCH / 128, 1);    // (133, 2, 1)
        gemm_bf16_tc<false><<<grid, 256, GEMM_SMEM>>>(
            h_hi, h_lo, ip_hi, ip_lo, zx,
            BATCH, D_IN_PROJ, D_MODEL, D_MODEL);
    }

    // 2) conv step
    {
        dim3 grid(CONV_DIM / 256, BATCH, 1);
        conv_kernel<<<grid, 256>>>(conv_in, conv_w, conv_b, conv_p);
    }

    // 3) fused SSM update + y*silu(z) (emits bf16 hi/lo yz)
    {
        dim3 grid(NHEADS, BATCH, 1);
        ssm_kernel<<<grid, 256>>>(ssm_in, dt_bias, A_log, Dvec, ssm_p);
    }

    // 4) out_proj: out[256,2048] = yz @ out_w^T   (split-K=4, atomic)
    {
        dim3 grid(D_MODEL / 64, BATCH / 128, 4);      // (32, 2, 4)
        gemm_bf16_tc<true><<<grid, 256, GEMM_SMEM>>>(
            yz_hi, yz_lo, op_hi, op_lo, out_p,
            BATCH, D_MODEL, D_SSM, D_SSM / 4);
    }
}